// round 1
// baseline (speedup 1.0000x reference)
#include <cuda_runtime.h>
#include <cuda_bf16.h>

// Haar wavelet 2x2 transform.
// Input:  x[B=8, C=64, H=512, W=512] fp32
// Output: out[B=8, 4*C=256, H/2=256, W/2=256] fp32
// out channel = 4*c + band, band in {ll, lh, hl, hh}.

#define B_ 8
#define C_ 64
#define H_ 512
#define W_ 512
#define H2_ (H_ / 2)
#define W2_ (W_ / 2)
#define COLS_PER_THREAD 4           // output columns per thread (= float4 store)
#define WGROUPS (W2_ / COLS_PER_THREAD)  // 64 column-groups per output row

__global__ __launch_bounds__(256)
void haar_kernel(const float* __restrict__ x, float* __restrict__ out) {
    // Flat index over (b, c, h2, wgroup)
    long long idx = (long long)blockIdx.x * blockDim.x + threadIdx.x;
    // total = B*C*H2*WGROUPS = 8*64*256*64 = 8,388,608
    int wg = (int)(idx % WGROUPS);
    long long t = idx / WGROUPS;
    int h2 = (int)(t % H2_);
    t /= H2_;
    int c = (int)(t % C_);
    int b = (int)(t / C_);

    // Input base: row 2*h2, col 2*COLS_PER_THREAD*wg
    const long long in_plane = (long long)(b * C_ + c) * (H_ * W_);
    const long long in_row0 = in_plane + (long long)(2 * h2) * W_ + 2 * COLS_PER_THREAD * wg;
    const long long in_row1 = in_row0 + W_;

    // 8 consecutive floats per row = 2x float4
    float4 r0a = *reinterpret_cast<const float4*>(x + in_row0);
    float4 r0b = *reinterpret_cast<const float4*>(x + in_row0 + 4);
    float4 r1a = *reinterpret_cast<const float4*>(x + in_row1);
    float4 r1b = *reinterpret_cast<const float4*>(x + in_row1 + 4);

    // pairs j=0..3: x00=row0[2j], x01=row0[2j+1], x10=row1[2j], x11=row1[2j+1]
    float x00[4] = {r0a.x, r0a.z, r0b.x, r0b.z};
    float x01[4] = {r0a.y, r0a.w, r0b.y, r0b.w};
    float x10[4] = {r1a.x, r1a.z, r1b.x, r1b.z};
    float x11[4] = {r1a.y, r1a.w, r1b.y, r1b.w};

    float4 ll, lh, hl, hh;
    float* llp = &ll.x; float* lhp = &lh.x; float* hlp = &hl.x; float* hhp = &hh.x;
    #pragma unroll
    for (int j = 0; j < 4; ++j) {
        float s0 = x00[j] + x01[j];
        float s1 = x10[j] + x11[j];
        float d0 = x01[j] - x00[j];
        float d1 = x11[j] - x10[j];
        llp[j] = 0.5f * (s0 + s1);
        lhp[j] = 0.5f * (s1 - s0);
        hlp[j] = 0.5f * (d0 + d1);
        hhp[j] = 0.5f * (d1 - d0);
    }

    // Output: plane index (b, 4*c + band), row h2, col COLS_PER_THREAD*wg
    const long long out_base =
        ((long long)(b * (4 * C_) + 4 * c) * H2_ + h2) * W2_ + COLS_PER_THREAD * wg;
    const long long plane_stride = (long long)H2_ * W2_;

    *reinterpret_cast<float4*>(out + out_base)                    = ll;
    *reinterpret_cast<float4*>(out + out_base + plane_stride)     = lh;
    *reinterpret_cast<float4*>(out + out_base + 2 * plane_stride) = hl;
    *reinterpret_cast<float4*>(out + out_base + 3 * plane_stride) = hh;
}

extern "C" void kernel_launch(void* const* d_in, const int* in_sizes, int n_in,
                              void* d_out, int out_size) {
    const float* x = (const float*)d_in[0];
    float* out = (float*)d_out;
    const long long total_threads = (long long)B_ * C_ * H2_ * WGROUPS; // 8,388,608
    const int threads = 256;
    const int blocks = (int)((total_threads + threads - 1) / threads); // 32768
    haar_kernel<<<blocks, threads>>>(x, out);
}